// round 9
// baseline (speedup 1.0000x reference)
#include <cuda_runtime.h>
#include <cuda_bf16.h>
#include <cstdint>
#include <cstddef>

#define BL_EPS 1e-5f
static constexpr int    M_ROWS  = 8192;
static constexpr int    KD      = 4096;
static constexpr int    ND      = 16384;
static constexpr size_t W_ELEMS = (size_t)ND * KD;
static constexpr size_t X_ELEMS = (size_t)M_ROWS * KD;

// scratch (device globals: no allocations allowed)
__device__ __nv_bfloat16 bl_qx[X_ELEMS];   // quantized activations (integers in bf16)
__device__ __nv_bfloat16 bl_wq[W_ELEMS];   // ternary weights {-1,0,1} in bf16
__device__ float bl_rs[M_ROWS];            // per-row amax/127
__device__ float bl_part[2048];
__device__ float bl_wp[1];                 // clip(mean|w|, eps)

// ---------------- helpers ----------------
__device__ __forceinline__ uint32_t bl_cvta_s(const void* p) {
    uint32_t a;
    asm("{ .reg .u64 t; cvta.to.shared.u64 t, %1; cvt.u32.u64 %0, t; }" : "=r"(a) : "l"(p));
    return a;
}
__device__ __forceinline__ void bl_cp16(uint32_t s, const void* g) {
    asm volatile("cp.async.cg.shared.global [%0], [%1], 16;" :: "r"(s), "l"(g));
}
__device__ __forceinline__ void bl_cp_commit() { asm volatile("cp.async.commit_group;"); }
template <int N> __device__ __forceinline__ void bl_cp_wait() {
    asm volatile("cp.async.wait_group %0;" :: "n"(N));
}
#define BL_LDSM4(r0, r1, r2, r3, a)                                              \
    asm volatile("ldmatrix.sync.aligned.m8n8.x4.shared.b16 {%0,%1,%2,%3}, [%4];" \
                 : "=r"(r0), "=r"(r1), "=r"(r2), "=r"(r3) : "r"(a))
#define BL_MMA_BF16(d, a0, a1, a2, a3, b0, b1)                                   \
    asm volatile("mma.sync.aligned.m16n8k16.row.col.f32.bf16.bf16.f32 "          \
                 "{%0,%1,%2,%3}, {%4,%5,%6,%7}, {%8,%9}, {%0,%1,%2,%3};"         \
                 : "+f"((d)[0]), "+f"((d)[1]), "+f"((d)[2]), "+f"((d)[3])        \
                 : "r"(a0), "r"(a1), "r"(a2), "r"(a3), "r"(b0), "r"(b1))

__device__ __forceinline__ uint32_t bl_packbf2(float a, float b) {
    return (uint32_t)__bfloat16_as_ushort(__float2bfloat16_rn(a))
         | ((uint32_t)__bfloat16_as_ushort(__float2bfloat16_rn(b)) << 16);
}

// ---------------- prep kernels ----------------
__global__ void bl_k_wabs(const float* __restrict__ w) {
    __shared__ float red[256];
    const float4* w4 = (const float4*)w;
    const size_t n4 = W_ELEMS / 4;
    float s = 0.f;
    for (size_t i = (size_t)blockIdx.x * 256 + threadIdx.x; i < n4; i += (size_t)2048 * 256) {
        float4 v = w4[i];
        s += fabsf(v.x) + fabsf(v.y) + fabsf(v.z) + fabsf(v.w);
    }
    red[threadIdx.x] = s; __syncthreads();
    for (int o = 128; o > 0; o >>= 1) {
        if ((int)threadIdx.x < o) red[threadIdx.x] += red[threadIdx.x + o];
        __syncthreads();
    }
    if (threadIdx.x == 0) bl_part[blockIdx.x] = red[0];
}

// fused: every block reduces bl_part identically (deterministic), then quantizes.
__global__ void bl_k_wquant(const float* __restrict__ w) {
    __shared__ float red[256];
    float s = 0.f;
#pragma unroll
    for (int i = 0; i < 8; i++) s += bl_part[threadIdx.x * 8 + i];
    red[threadIdx.x] = s; __syncthreads();
    for (int o = 128; o > 0; o >>= 1) {
        if ((int)threadIdx.x < o) red[threadIdx.x] += red[threadIdx.x + o];
        __syncthreads();
    }
    const float m = fmaxf(red[0] / (float)W_ELEMS, BL_EPS);
    const float sc = 1.f / m;
    if (blockIdx.x == 0 && threadIdx.x == 0) bl_wp[0] = m;

    const float4* w4 = (const float4*)w;
    uint2* out = (uint2*)bl_wq;
    const size_t n4 = W_ELEMS / 4;
    for (size_t i = (size_t)blockIdx.x * 256 + threadIdx.x; i < n4; i += (size_t)2048 * 256) {
        float4 v = w4[i];
        float q0 = fminf(fmaxf(rintf(v.x * sc), -1.f), 1.f);
        float q1 = fminf(fmaxf(rintf(v.y * sc), -1.f), 1.f);
        float q2 = fminf(fmaxf(rintf(v.z * sc), -1.f), 1.f);
        float q3 = fminf(fmaxf(rintf(v.w * sc), -1.f), 1.f);
        uint2 o;
        o.x = bl_packbf2(q0, q1);
        o.y = bl_packbf2(q2, q3);
        out[i] = o;
    }
}

__global__ void bl_k_aquant(const float* __restrict__ x) {
    __shared__ float red[256];
    const int row = blockIdx.x;
    const float4* xr = (const float4*)(x + (size_t)row * KD);
    float4 v[4];
    float mx = 0.f;
#pragma unroll
    for (int i = 0; i < 4; i++) {
        v[i] = xr[threadIdx.x + i * 256];
        mx = fmaxf(mx, fmaxf(fmaxf(fabsf(v[i].x), fabsf(v[i].y)),
                             fmaxf(fabsf(v[i].z), fabsf(v[i].w))));
    }
    red[threadIdx.x] = mx; __syncthreads();
    for (int o = 128; o > 0; o >>= 1) {
        if ((int)threadIdx.x < o) red[threadIdx.x] = fmaxf(red[threadIdx.x], red[threadIdx.x + o]);
        __syncthreads();
    }
    const float amax  = fmaxf(red[0], BL_EPS);
    const float scale = 127.f / amax;
    if (threadIdx.x == 0) bl_rs[row] = amax * (1.f / 127.f);
    uint2* qr = (uint2*)(bl_qx + (size_t)row * KD);
#pragma unroll
    for (int i = 0; i < 4; i++) {
        float q0 = fminf(fmaxf(rintf(v[i].x * scale), -128.f), 127.f);
        float q1 = fminf(fmaxf(rintf(v[i].y * scale), -128.f), 127.f);
        float q2 = fminf(fmaxf(rintf(v[i].z * scale), -128.f), 127.f);
        float q3 = fminf(fmaxf(rintf(v[i].w * scale), -128.f), 127.f);
        uint2 o;
        o.x = bl_packbf2(q0, q1);
        o.y = bl_packbf2(q2, q3);
        qr[threadIdx.x + i * 256] = o;
    }
}

// ---------------- bf16 HMMA GEMM ----------------
// CTA tile 128(M) x 256(N), BK = 64 bf16 (128 B rows), 3-stage cp.async.
// 8 warps (256 thr), warp grid 2(M) x 4(N), warp tile 64 x 64.
static constexpr int BM = 128, BN = 256, BKE = 64;
static constexpr int KCH   = KD / BKE;               // 64 chunks
static constexpr int A_B   = BM * 128;               // 16 KB
static constexpr int B_B   = BN * 128;               // 32 KB
static constexpr int STG   = A_B + B_B;              // 48 KB
static constexpr int SMEM_SZ = 3 * STG;              // 147456

#define BL_SWZ_MASK(row) ((uint32_t)(((row) & 7) << 4))

__device__ __forceinline__ void bl_load_stage(uint32_t base, const __nv_bfloat16* a,
                                              const __nv_bfloat16* b, int tid) {
#pragma unroll
    for (int i = 0; i < 4; i++) {            // A: 128 rows x 128 B = 1024 x 16 B
        int s = tid + i * 256;
        int rr = s >> 3, j = s & 7;
        uint32_t off = (uint32_t)(rr * 128 + j * 16);
        bl_cp16(base + (off ^ BL_SWZ_MASK(rr)), a + (size_t)rr * KD + j * 8);
    }
    uint32_t bb = base + A_B;
#pragma unroll
    for (int i = 0; i < 8; i++) {            // B: 256 rows x 128 B = 2048 x 16 B
        int s = tid + i * 256;
        int rr = s >> 3, j = s & 7;
        uint32_t off = (uint32_t)(rr * 128 + j * 16);
        bl_cp16(bb + (off ^ BL_SWZ_MASK(rr)), b + (size_t)rr * KD + j * 8);
    }
}

__global__ void __launch_bounds__(256, 1) bl_k_gemm(float* __restrict__ out) {
    extern __shared__ char smem[];
    const uint32_t sb = bl_cvta_s(smem);
    const int tid  = threadIdx.x;
    const int wid  = tid >> 5, lane = tid & 31;
    const int warp_m = wid & 1;              // 0..1 -> 64 rows
    const int warp_n = wid >> 1;             // 0..3 -> 64 cols

    // supertile swizzle: bands of 8 M-tiles, sweep all 64 N-tiles per band
    const int bid  = blockIdx.x;
    const int band = bid >> 9;
    const int r    = bid & 511;
    const int mt_  = band * 8 + (r & 7);
    const int nt_  = r >> 3;
    const int m0 = mt_ * BM, n0 = nt_ * BN;

    const __nv_bfloat16* A = bl_qx + (size_t)m0 * KD;
    const __nv_bfloat16* B = bl_wq + (size_t)n0 * KD;

    bl_load_stage(sb + 0 * STG, A, B, tid);              bl_cp_commit();
    bl_load_stage(sb + 1 * STG, A + BKE, B + BKE, tid);  bl_cp_commit();

    // ldmatrix lane addressing (16-B granule swizzle; 16 B = 8 bf16 = k8)
    const int lm = lane >> 3;                // matrix 0..3 within .x4
    const int l8 = lane & 7;
    // A matrices: {r+0 k0-7}, {r+8 k0-7}, {r+0 k8-15}, {r+8 k8-15} -> a0..a3
    const int a_row  = warp_m * 64 + (lm & 1) * 8 + l8;
    const uint32_t a_xor  = BL_SWZ_MASK(a_row);
    const uint32_t a_base = (uint32_t)(a_row * 128) + (uint32_t)((lm >> 1) * 16);
    // B matrices: {n+0 k0-7}, {n+0 k8-15}, {n+8 k0-7}, {n+8 k8-15}
    const int b_row  = warp_n * 64 + (lm >> 1) * 8 + l8;
    const uint32_t b_xor  = BL_SWZ_MASK(b_row);
    const uint32_t b_base = (uint32_t)(b_row * 128) + (uint32_t)((lm & 1) * 16);

    float acc[4][8][4];
#pragma unroll
    for (int i = 0; i < 4; i++)
#pragma unroll
        for (int j = 0; j < 8; j++)
#pragma unroll
            for (int q = 0; q < 4; q++) acc[i][j][q] = 0.f;

    for (int kc = 0; kc < KCH; kc++) {
        bl_cp_wait<1>();
        __syncthreads();
        const int kn = kc + 2;
        if (kn < KCH)
            bl_load_stage(sb + (kn % 3) * STG, A + (size_t)kn * BKE,
                          B + (size_t)kn * BKE, tid);
        bl_cp_commit();

        const uint32_t abuf = sb + (kc % 3) * STG;
        const uint32_t bbuf = abuf + A_B;
#pragma unroll
        for (int ks = 0; ks < 4; ks++) {     // 4 x k16 steps (32 B each)
            uint32_t af[4][4];
#pragma unroll
            for (int mt = 0; mt < 4; mt++) {
                uint32_t ad = abuf + ((a_base + (uint32_t)(mt * 16 * 128)
                                        + (uint32_t)(ks * 32)) ^ a_xor);
                BL_LDSM4(af[mt][0], af[mt][1], af[mt][2], af[mt][3], ad);
            }
            uint32_t bf[8][2];
#pragma unroll
            for (int nt2 = 0; nt2 < 4; nt2++) {
                uint32_t bd = bbuf + ((b_base + (uint32_t)(nt2 * 16 * 128)
                                        + (uint32_t)(ks * 32)) ^ b_xor);
                uint32_t r0, r1, r2, r3;
                BL_LDSM4(r0, r1, r2, r3, bd);
                bf[nt2 * 2 + 0][0] = r0; bf[nt2 * 2 + 0][1] = r1;
                bf[nt2 * 2 + 1][0] = r2; bf[nt2 * 2 + 1][1] = r3;
            }
#pragma unroll
            for (int mt = 0; mt < 4; mt++)
#pragma unroll
                for (int nt = 0; nt < 8; nt++)
                    BL_MMA_BF16(acc[mt][nt], af[mt][0], af[mt][1], af[mt][2],
                                af[mt][3], bf[nt][0], bf[nt][1]);
        }
    }

    // epilogue: scale fp32 (exact integers) by rs[row] * mean|w|
    const float wp0 = bl_wp[0];
    const int gr = lane >> 2;
    const int gc = (lane & 3) * 2;
#pragma unroll
    for (int mt = 0; mt < 4; mt++) {
        const int row0 = m0 + warp_m * 64 + mt * 16 + gr;
        const int row1 = row0 + 8;
        const float s0 = bl_rs[row0] * wp0;
        const float s1 = bl_rs[row1] * wp0;
        float* p0 = out + (size_t)row0 * ND + n0 + warp_n * 64 + gc;
        float* p1 = out + (size_t)row1 * ND + n0 + warp_n * 64 + gc;
#pragma unroll
        for (int nt = 0; nt < 8; nt++) {
            *(float2*)(p0 + nt * 8) = make_float2(acc[mt][nt][0] * s0,
                                                  acc[mt][nt][1] * s0);
            *(float2*)(p1 + nt * 8) = make_float2(acc[mt][nt][2] * s1,
                                                  acc[mt][nt][3] * s1);
        }
    }
}

// ---------------- launcher ----------------
extern "C" void kernel_launch(void* const* d_in, const int* in_sizes, int n_in,
                              void* d_out, int out_size) {
    const float* x = (const float*)d_in[0];
    const float* w = (const float*)d_in[1];
    float* out = (float*)d_out;
    cudaFuncSetAttribute(bl_k_gemm, cudaFuncAttributeMaxDynamicSharedMemorySize, SMEM_SZ);
    bl_k_wabs<<<2048, 256>>>(w);
    bl_k_wquant<<<2048, 256>>>(w);
    bl_k_aquant<<<M_ROWS, 256>>>(x);
    bl_k_gemm<<<(M_ROWS / BM) * (ND / BN), 256, SMEM_SZ>>>(out);
}

// round 10
// speedup vs baseline: 1.6323x; 1.6323x over previous
#include <cuda_runtime.h>
#include <cuda_bf16.h>
#include <cstdint>
#include <cstddef>

#define BL_EPS 1e-5f
static constexpr int    M_ROWS  = 8192;
static constexpr int    KD      = 4096;
static constexpr int    ND      = 16384;
static constexpr size_t W_ELEMS = (size_t)ND * KD;
static constexpr size_t X_ELEMS = (size_t)M_ROWS * KD;

// scratch (device globals: no allocations allowed)
__device__ __nv_bfloat16 bl_qx[X_ELEMS];   // quantized activations (integers in bf16)
__device__ __nv_bfloat16 bl_wq[W_ELEMS];   // ternary weights {-1,0,1} in bf16
__device__ float bl_rs[M_ROWS];            // per-row amax/127
__device__ float bl_part[2048];
__device__ float bl_wp[1];                 // clip(mean|w|, eps)

// ---------------- helpers ----------------
__device__ __forceinline__ uint32_t bl_cvta_s(const void* p) {
    uint32_t a;
    asm("{ .reg .u64 t; cvta.to.shared.u64 t, %1; cvt.u32.u64 %0, t; }" : "=r"(a) : "l"(p));
    return a;
}
__device__ __forceinline__ void bl_cp16(uint32_t s, const void* g) {
    asm volatile("cp.async.cg.shared.global [%0], [%1], 16;" :: "r"(s), "l"(g));
}
__device__ __forceinline__ void bl_cp_commit() { asm volatile("cp.async.commit_group;"); }
template <int N> __device__ __forceinline__ void bl_cp_wait() {
    asm volatile("cp.async.wait_group %0;" :: "n"(N));
}
#define BL_LDSM4(r0, r1, r2, r3, a)                                              \
    asm volatile("ldmatrix.sync.aligned.m8n8.x4.shared.b16 {%0,%1,%2,%3}, [%4];" \
                 : "=r"(r0), "=r"(r1), "=r"(r2), "=r"(r3) : "r"(a))
#define BL_MMA_BF16(d, a0, a1, a2, a3, b0, b1)                                   \
    asm volatile("mma.sync.aligned.m16n8k16.row.col.f32.bf16.bf16.f32 "          \
                 "{%0,%1,%2,%3}, {%4,%5,%6,%7}, {%8,%9}, {%0,%1,%2,%3};"         \
                 : "+f"((d)[0]), "+f"((d)[1]), "+f"((d)[2]), "+f"((d)[3])        \
                 : "r"(a0), "r"(a1), "r"(a2), "r"(a3), "r"(b0), "r"(b1))

__device__ __forceinline__ uint32_t bl_packbf2(float a, float b) {
    return (uint32_t)__bfloat16_as_ushort(__float2bfloat16_rn(a))
         | ((uint32_t)__bfloat16_as_ushort(__float2bfloat16_rn(b)) << 16);
}

// ---------------- prep kernels ----------------
__global__ void bl_k_wabs(const float* __restrict__ w) {
    __shared__ float red[256];
    const float4* w4 = (const float4*)w;
    const size_t n4 = W_ELEMS / 4;
    float s = 0.f;
    for (size_t i = (size_t)blockIdx.x * 256 + threadIdx.x; i < n4; i += (size_t)2048 * 256) {
        float4 v = w4[i];
        s += fabsf(v.x) + fabsf(v.y) + fabsf(v.z) + fabsf(v.w);
    }
    red[threadIdx.x] = s; __syncthreads();
    for (int o = 128; o > 0; o >>= 1) {
        if ((int)threadIdx.x < o) red[threadIdx.x] += red[threadIdx.x + o];
        __syncthreads();
    }
    if (threadIdx.x == 0) bl_part[blockIdx.x] = red[0];
}

// fused: every block reduces bl_part identically (deterministic), then quantizes.
__global__ void bl_k_wquant(const float* __restrict__ w) {
    __shared__ float red[256];
    float s = 0.f;
#pragma unroll
    for (int i = 0; i < 8; i++) s += bl_part[threadIdx.x * 8 + i];
    red[threadIdx.x] = s; __syncthreads();
    for (int o = 128; o > 0; o >>= 1) {
        if ((int)threadIdx.x < o) red[threadIdx.x] += red[threadIdx.x + o];
        __syncthreads();
    }
    const float m = fmaxf(red[0] / (float)W_ELEMS, BL_EPS);
    const float sc = 1.f / m;
    if (blockIdx.x == 0 && threadIdx.x == 0) bl_wp[0] = m;

    const float4* w4 = (const float4*)w;
    uint2* out = (uint2*)bl_wq;
    const size_t n4 = W_ELEMS / 4;
    for (size_t i = (size_t)blockIdx.x * 256 + threadIdx.x; i < n4; i += (size_t)2048 * 256) {
        float4 v = w4[i];
        float q0 = fminf(fmaxf(rintf(v.x * sc), -1.f), 1.f);
        float q1 = fminf(fmaxf(rintf(v.y * sc), -1.f), 1.f);
        float q2 = fminf(fmaxf(rintf(v.z * sc), -1.f), 1.f);
        float q3 = fminf(fmaxf(rintf(v.w * sc), -1.f), 1.f);
        uint2 o;
        o.x = bl_packbf2(q0, q1);
        o.y = bl_packbf2(q2, q3);
        out[i] = o;
    }
}

__global__ void bl_k_aquant(const float* __restrict__ x) {
    __shared__ float red[256];
    const int row = blockIdx.x;
    const float4* xr = (const float4*)(x + (size_t)row * KD);
    float4 v[4];
    float mx = 0.f;
#pragma unroll
    for (int i = 0; i < 4; i++) {
        v[i] = xr[threadIdx.x + i * 256];
        mx = fmaxf(mx, fmaxf(fmaxf(fabsf(v[i].x), fabsf(v[i].y)),
                             fmaxf(fabsf(v[i].z), fabsf(v[i].w))));
    }
    red[threadIdx.x] = mx; __syncthreads();
    for (int o = 128; o > 0; o >>= 1) {
        if ((int)threadIdx.x < o) red[threadIdx.x] = fmaxf(red[threadIdx.x], red[threadIdx.x + o]);
        __syncthreads();
    }
    const float amax  = fmaxf(red[0], BL_EPS);
    const float scale = 127.f / amax;
    if (threadIdx.x == 0) bl_rs[row] = amax * (1.f / 127.f);
    uint2* qr = (uint2*)(bl_qx + (size_t)row * KD);
#pragma unroll
    for (int i = 0; i < 4; i++) {
        float q0 = fminf(fmaxf(rintf(v[i].x * scale), -128.f), 127.f);
        float q1 = fminf(fmaxf(rintf(v[i].y * scale), -128.f), 127.f);
        float q2 = fminf(fmaxf(rintf(v[i].z * scale), -128.f), 127.f);
        float q3 = fminf(fmaxf(rintf(v[i].w * scale), -128.f), 127.f);
        uint2 o;
        o.x = bl_packbf2(q0, q1);
        o.y = bl_packbf2(q2, q3);
        qr[threadIdx.x + i * 256] = o;
    }
}

// ---------------- bf16 HMMA GEMM ----------------
// CTA tile 128(M) x 128(N), BK = 64 bf16 (128 B rows), 3-stage cp.async.
// 8 warps (256 thr), warp grid 2(M) x 4(N), warp tile 64 x 32.
// 2 CTAs per SM overlap each other's chunk-boundary bubbles.
static constexpr int BM = 128, BN = 128, BKE = 64;
static constexpr int KCH   = KD / BKE;               // 64 chunks
static constexpr int A_B   = BM * 128;               // 16 KB
static constexpr int B_B   = BN * 128;               // 16 KB
static constexpr int STG   = A_B + B_B;              // 32 KB
static constexpr int SMEM_SZ = 3 * STG;              // 98304 (x2 CTAs = 192 KB/SM)

#define BL_SWZ_MASK(row) ((uint32_t)(((row) & 7) << 4))

__device__ __forceinline__ void bl_load_stage(uint32_t base, const __nv_bfloat16* a,
                                              const __nv_bfloat16* b, int tid) {
#pragma unroll
    for (int i = 0; i < 4; i++) {            // A: 128 rows x 128 B = 1024 x 16 B
        int s = tid + i * 256;
        int rr = s >> 3, j = s & 7;
        uint32_t off = (uint32_t)(rr * 128 + j * 16);
        bl_cp16(base + (off ^ BL_SWZ_MASK(rr)), a + (size_t)rr * KD + j * 8);
    }
    uint32_t bb = base + A_B;
#pragma unroll
    for (int i = 0; i < 4; i++) {            // B: 128 rows x 128 B
        int s = tid + i * 256;
        int rr = s >> 3, j = s & 7;
        uint32_t off = (uint32_t)(rr * 128 + j * 16);
        bl_cp16(bb + (off ^ BL_SWZ_MASK(rr)), b + (size_t)rr * KD + j * 8);
    }
}

__global__ void __launch_bounds__(256, 2) bl_k_gemm(float* __restrict__ out) {
    extern __shared__ char smem[];
    const uint32_t sb = bl_cvta_s(smem);
    const int tid  = threadIdx.x;
    const int wid  = tid >> 5, lane = tid & 31;
    const int warp_m = wid & 1;              // 0..1 -> 64 rows
    const int warp_n = wid >> 1;             // 0..3 -> 32 cols

    // supertile swizzle: bands of 16 M-tiles, sweep all 128 N-tiles per band
    const int bid  = blockIdx.x;
    const int band = bid >> 11;              // / (16*128)
    const int r    = bid & 2047;
    const int mt_  = band * 16 + (r & 15);
    const int nt_  = r >> 4;
    const int m0 = mt_ * BM, n0 = nt_ * BN;

    const __nv_bfloat16* A = bl_qx + (size_t)m0 * KD;
    const __nv_bfloat16* B = bl_wq + (size_t)n0 * KD;

    bl_load_stage(sb + 0 * STG, A, B, tid);              bl_cp_commit();
    bl_load_stage(sb + 1 * STG, A + BKE, B + BKE, tid);  bl_cp_commit();

    // ldmatrix lane addressing (16-B granule swizzle; 16 B = 8 bf16 = k8)
    const int lm = lane >> 3;                // matrix 0..3 within .x4
    const int l8 = lane & 7;
    // A matrices: {r+0 k0-7}, {r+8 k0-7}, {r+0 k8-15}, {r+8 k8-15} -> a0..a3
    const int a_row  = warp_m * 64 + (lm & 1) * 8 + l8;
    const uint32_t a_xor  = BL_SWZ_MASK(a_row);
    const uint32_t a_base = (uint32_t)(a_row * 128) + (uint32_t)((lm >> 1) * 16);
    // B matrices: {n+0 k0-7}, {n+0 k8-15}, {n+8 k0-7}, {n+8 k8-15}
    const int b_row  = warp_n * 32 + (lm >> 1) * 8 + l8;
    const uint32_t b_xor  = BL_SWZ_MASK(b_row);
    const uint32_t b_base = (uint32_t)(b_row * 128) + (uint32_t)((lm & 1) * 16);

    float acc[4][4][4];
#pragma unroll
    for (int i = 0; i < 4; i++)
#pragma unroll
        for (int j = 0; j < 4; j++)
#pragma unroll
            for (int q = 0; q < 4; q++) acc[i][j][q] = 0.f;

    for (int kc = 0; kc < KCH; kc++) {
        bl_cp_wait<1>();
        __syncthreads();
        const int kn = kc + 2;
        if (kn < KCH)
            bl_load_stage(sb + (kn % 3) * STG, A + (size_t)kn * BKE,
                          B + (size_t)kn * BKE, tid);
        bl_cp_commit();

        const uint32_t abuf = sb + (kc % 3) * STG;
        const uint32_t bbuf = abuf + A_B;
#pragma unroll
        for (int ks = 0; ks < 4; ks++) {     // 4 x k16 steps (32 B each)
            uint32_t af[4][4];
#pragma unroll
            for (int mt = 0; mt < 4; mt++) {
                uint32_t ad = abuf + ((a_base + (uint32_t)(mt * 16 * 128)
                                        + (uint32_t)(ks * 32)) ^ a_xor);
                BL_LDSM4(af[mt][0], af[mt][1], af[mt][2], af[mt][3], ad);
            }
            uint32_t bf[4][2];
#pragma unroll
            for (int nt2 = 0; nt2 < 2; nt2++) {
                uint32_t bd = bbuf + ((b_base + (uint32_t)(nt2 * 16 * 128)
                                        + (uint32_t)(ks * 32)) ^ b_xor);
                uint32_t r0, r1, r2, r3;
                BL_LDSM4(r0, r1, r2, r3, bd);
                bf[nt2 * 2 + 0][0] = r0; bf[nt2 * 2 + 0][1] = r1;
                bf[nt2 * 2 + 1][0] = r2; bf[nt2 * 2 + 1][1] = r3;
            }
#pragma unroll
            for (int mt = 0; mt < 4; mt++)
#pragma unroll
                for (int nt = 0; nt < 4; nt++)
                    BL_MMA_BF16(acc[mt][nt], af[mt][0], af[mt][1], af[mt][2],
                                af[mt][3], bf[nt][0], bf[nt][1]);
        }
    }

    // epilogue: scale fp32 (exact integers) by rs[row] * mean|w|
    const float wp0 = bl_wp[0];
    const int gr = lane >> 2;
    const int gc = (lane & 3) * 2;
#pragma unroll
    for (int mt = 0; mt < 4; mt++) {
        const int row0 = m0 + warp_m * 64 + mt * 16 + gr;
        const int row1 = row0 + 8;
        const float s0 = bl_rs[row0] * wp0;
        const float s1 = bl_rs[row1] * wp0;
        float* p0 = out + (size_t)row0 * ND + n0 + warp_n * 32 + gc;
        float* p1 = out + (size_t)row1 * ND + n0 + warp_n * 32 + gc;
#pragma unroll
        for (int nt = 0; nt < 4; nt++) {
            *(float2*)(p0 + nt * 8) = make_float2(acc[mt][nt][0] * s0,
                                                  acc[mt][nt][1] * s0);
            *(float2*)(p1 + nt * 8) = make_float2(acc[mt][nt][2] * s1,
                                                  acc[mt][nt][3] * s1);
        }
    }
}

// ---------------- launcher ----------------
extern "C" void kernel_launch(void* const* d_in, const int* in_sizes, int n_in,
                              void* d_out, int out_size) {
    const float* x = (const float*)d_in[0];
    const float* w = (const float*)d_in[1];
    float* out = (float*)d_out;
    cudaFuncSetAttribute(bl_k_gemm, cudaFuncAttributeMaxDynamicSharedMemorySize, SMEM_SZ);
    bl_k_wabs<<<2048, 256>>>(w);
    bl_k_wquant<<<2048, 256>>>(w);
    bl_k_aquant<<<M_ROWS, 256>>>(x);
    bl_k_gemm<<<(M_ROWS / BM) * (ND / BN), 256, SMEM_SZ>>>(out);
}

// round 11
// speedup vs baseline: 1.6489x; 1.0101x over previous
#include <cuda_runtime.h>
#include <cuda_bf16.h>
#include <cstdint>
#include <cstddef>

#define BL_EPS 1e-5f
static constexpr int    M_ROWS  = 8192;
static constexpr int    KD      = 4096;
static constexpr int    ND      = 16384;
static constexpr size_t W_ELEMS = (size_t)ND * KD;
static constexpr size_t X_ELEMS = (size_t)M_ROWS * KD;

// scratch (device globals: no allocations allowed)
__device__ __nv_bfloat16 bl_qx[X_ELEMS];   // quantized activations (integers in bf16)
__device__ __nv_bfloat16 bl_wq[W_ELEMS];   // ternary weights {-1,0,1} in bf16
__device__ float bl_rs[M_ROWS];            // per-row amax/127
__device__ float bl_part[2048];
__device__ float bl_wp[1];                 // clip(mean|w|, eps)

// ---------------- helpers ----------------
__device__ __forceinline__ uint32_t bl_cvta_s(const void* p) {
    uint32_t a;
    asm("{ .reg .u64 t; cvta.to.shared.u64 t, %1; cvt.u32.u64 %0, t; }" : "=r"(a) : "l"(p));
    return a;
}
__device__ __forceinline__ void bl_cp16(uint32_t s, const void* g) {
    asm volatile("cp.async.cg.shared.global [%0], [%1], 16;" :: "r"(s), "l"(g));
}
__device__ __forceinline__ void bl_cp_commit() { asm volatile("cp.async.commit_group;"); }
template <int N> __device__ __forceinline__ void bl_cp_wait() {
    asm volatile("cp.async.wait_group %0;" :: "n"(N));
}
#define BL_LDSM4(r0, r1, r2, r3, a)                                              \
    asm volatile("ldmatrix.sync.aligned.m8n8.x4.shared.b16 {%0,%1,%2,%3}, [%4];" \
                 : "=r"(r0), "=r"(r1), "=r"(r2), "=r"(r3) : "r"(a))
#define BL_MMA_BF16(d, a0, a1, a2, a3, b0, b1)                                   \
    asm volatile("mma.sync.aligned.m16n8k16.row.col.f32.bf16.bf16.f32 "          \
                 "{%0,%1,%2,%3}, {%4,%5,%6,%7}, {%8,%9}, {%0,%1,%2,%3};"         \
                 : "+f"((d)[0]), "+f"((d)[1]), "+f"((d)[2]), "+f"((d)[3])        \
                 : "r"(a0), "r"(a1), "r"(a2), "r"(a3), "r"(b0), "r"(b1))

__device__ __forceinline__ uint32_t bl_packbf2(float a, float b) {
    return (uint32_t)__bfloat16_as_ushort(__float2bfloat16_rn(a))
         | ((uint32_t)__bfloat16_as_ushort(__float2bfloat16_rn(b)) << 16);
}

// ---------------- prep kernels ----------------
// fused launch 1: blocks [0,8192) = per-row activation quant; [8192,10240) = |w| partials
__global__ void bl_k_prep(const float* __restrict__ x, const float* __restrict__ w) {
    __shared__ float red[256];
    if (blockIdx.x >= 8192) {               // |w| partial sums
        const int pb = blockIdx.x - 8192;   // 0..2047
        const float4* w4 = (const float4*)w;
        const size_t n4 = W_ELEMS / 4;
        float s = 0.f;
        for (size_t i = (size_t)pb * 256 + threadIdx.x; i < n4; i += (size_t)2048 * 256) {
            float4 v = w4[i];
            s += fabsf(v.x) + fabsf(v.y) + fabsf(v.z) + fabsf(v.w);
        }
        red[threadIdx.x] = s; __syncthreads();
        for (int o = 128; o > 0; o >>= 1) {
            if ((int)threadIdx.x < o) red[threadIdx.x] += red[threadIdx.x + o];
            __syncthreads();
        }
        if (threadIdx.x == 0) bl_part[pb] = red[0];
        return;
    }
    // activation quant for one row
    const int row = blockIdx.x;
    const float4* xr = (const float4*)(x + (size_t)row * KD);
    float4 v[4];
    float mx = 0.f;
#pragma unroll
    for (int i = 0; i < 4; i++) {
        v[i] = xr[threadIdx.x + i * 256];
        mx = fmaxf(mx, fmaxf(fmaxf(fabsf(v[i].x), fabsf(v[i].y)),
                             fmaxf(fabsf(v[i].z), fabsf(v[i].w))));
    }
    red[threadIdx.x] = mx; __syncthreads();
    for (int o = 128; o > 0; o >>= 1) {
        if ((int)threadIdx.x < o) red[threadIdx.x] = fmaxf(red[threadIdx.x], red[threadIdx.x + o]);
        __syncthreads();
    }
    const float amax  = fmaxf(red[0], BL_EPS);
    const float scale = 127.f / amax;
    if (threadIdx.x == 0) bl_rs[row] = amax * (1.f / 127.f);
    uint2* qr = (uint2*)(bl_qx + (size_t)row * KD);
#pragma unroll
    for (int i = 0; i < 4; i++) {
        float q0 = fminf(fmaxf(rintf(v[i].x * scale), -128.f), 127.f);
        float q1 = fminf(fmaxf(rintf(v[i].y * scale), -128.f), 127.f);
        float q2 = fminf(fmaxf(rintf(v[i].z * scale), -128.f), 127.f);
        float q3 = fminf(fmaxf(rintf(v[i].w * scale), -128.f), 127.f);
        uint2 o;
        o.x = bl_packbf2(q0, q1);
        o.y = bl_packbf2(q2, q3);
        qr[threadIdx.x + i * 256] = o;
    }
}

// fused: every block reduces bl_part identically (deterministic), then quantizes.
__global__ void bl_k_wquant(const float* __restrict__ w) {
    __shared__ float red[256];
    float s = 0.f;
#pragma unroll
    for (int i = 0; i < 8; i++) s += bl_part[threadIdx.x * 8 + i];
    red[threadIdx.x] = s; __syncthreads();
    for (int o = 128; o > 0; o >>= 1) {
        if ((int)threadIdx.x < o) red[threadIdx.x] += red[threadIdx.x + o];
        __syncthreads();
    }
    const float m = fmaxf(red[0] / (float)W_ELEMS, BL_EPS);
    const float sc = 1.f / m;
    if (blockIdx.x == 0 && threadIdx.x == 0) bl_wp[0] = m;

    const float4* w4 = (const float4*)w;
    uint2* out = (uint2*)bl_wq;
    const size_t n4 = W_ELEMS / 4;
    for (size_t i = (size_t)blockIdx.x * 256 + threadIdx.x; i < n4; i += (size_t)2048 * 256) {
        float4 v = w4[i];
        float q0 = fminf(fmaxf(rintf(v.x * sc), -1.f), 1.f);
        float q1 = fminf(fmaxf(rintf(v.y * sc), -1.f), 1.f);
        float q2 = fminf(fmaxf(rintf(v.z * sc), -1.f), 1.f);
        float q3 = fminf(fmaxf(rintf(v.w * sc), -1.f), 1.f);
        uint2 o;
        o.x = bl_packbf2(q0, q1);
        o.y = bl_packbf2(q2, q3);
        out[i] = o;
    }
}

// ---------------- bf16 HMMA GEMM ----------------
// CTA tile 128(M) x 128(N), BK = 64 bf16 (128 B rows), 3-stage cp.async.
// 8 warps (256 thr), warp grid 2(M) x 4(N), warp tile 64 x 32.
// 2 CTAs per SM; co-resident pair staggered by ~half a chunk so their
// per-chunk barrier bubbles interleave instead of aligning.
static constexpr int BM = 128, BN = 128, BKE = 64;
static constexpr int KCH   = KD / BKE;               // 64 chunks
static constexpr int A_B   = BM * 128;               // 16 KB
static constexpr int B_B   = BN * 128;               // 16 KB
static constexpr int STG   = A_B + B_B;              // 32 KB
static constexpr int SMEM_SZ = 3 * STG;              // 98304 (x2 CTAs = 192 KB/SM)

#define BL_SWZ_MASK(row) ((uint32_t)(((row) & 7) << 4))

__device__ __forceinline__ void bl_load_stage(uint32_t base, const __nv_bfloat16* a,
                                              const __nv_bfloat16* b, int tid) {
#pragma unroll
    for (int i = 0; i < 4; i++) {            // A: 128 rows x 128 B = 1024 x 16 B
        int s = tid + i * 256;
        int rr = s >> 3, j = s & 7;
        uint32_t off = (uint32_t)(rr * 128 + j * 16);
        bl_cp16(base + (off ^ BL_SWZ_MASK(rr)), a + (size_t)rr * KD + j * 8);
    }
    uint32_t bb = base + A_B;
#pragma unroll
    for (int i = 0; i < 4; i++) {            // B: 128 rows x 128 B
        int s = tid + i * 256;
        int rr = s >> 3, j = s & 7;
        uint32_t off = (uint32_t)(rr * 128 + j * 16);
        bl_cp16(bb + (off ^ BL_SWZ_MASK(rr)), b + (size_t)rr * KD + j * 8);
    }
}

__global__ void __launch_bounds__(256, 2) bl_k_gemm(float* __restrict__ out) {
    extern __shared__ char smem[];
    const uint32_t sb = bl_cvta_s(smem);
    const int tid  = threadIdx.x;
    const int wid  = tid >> 5, lane = tid & 31;
    const int warp_m = wid & 1;              // 0..1 -> 64 rows
    const int warp_n = wid >> 1;             // 0..3 -> 32 cols

    // supertile swizzle: bands of 16 M-tiles, sweep all 128 N-tiles per band
    const int bid  = blockIdx.x;
    const int band = bid >> 11;              // / (16*128)
    const int r    = bid & 2047;
    const int mt_  = band * 16 + (r & 15);
    const int nt_  = r >> 4;
    const int m0 = mt_ * BM, n0 = nt_ * BN;

    const __nv_bfloat16* A = bl_qx + (size_t)m0 * KD;
    const __nv_bfloat16* B = bl_wq + (size_t)n0 * KD;

    bl_load_stage(sb + 0 * STG, A, B, tid);              bl_cp_commit();
    bl_load_stage(sb + 1 * STG, A + BKE, B + BKE, tid);  bl_cp_commit();

    // Phase-stagger one CTA of each co-resident pair (classic placement pairs
    // bid with bid+148). Timing-only: output is unaffected.
    if (((bid / 148) & 1) != 0) {
        unsigned long long t0 = clock64();
        while (clock64() - t0 < 1000ull) {}
    }

    // ldmatrix lane addressing (16-B granule swizzle; 16 B = 8 bf16 = k8)
    const int lm = lane >> 3;                // matrix 0..3 within .x4
    const int l8 = lane & 7;
    // A matrices: {r+0 k0-7}, {r+8 k0-7}, {r+0 k8-15}, {r+8 k8-15} -> a0..a3
    const int a_row  = warp_m * 64 + (lm & 1) * 8 + l8;
    const uint32_t a_xor  = BL_SWZ_MASK(a_row);
    const uint32_t a_base = (uint32_t)(a_row * 128) + (uint32_t)((lm >> 1) * 16);
    // B matrices: {n+0 k0-7}, {n+0 k8-15}, {n+8 k0-7}, {n+8 k8-15}
    const int b_row  = warp_n * 32 + (lm >> 1) * 8 + l8;
    const uint32_t b_xor  = BL_SWZ_MASK(b_row);
    const uint32_t b_base = (uint32_t)(b_row * 128) + (uint32_t)((lm & 1) * 16);

    float acc[4][4][4];
#pragma unroll
    for (int i = 0; i < 4; i++)
#pragma unroll
        for (int j = 0; j < 4; j++)
#pragma unroll
            for (int q = 0; q < 4; q++) acc[i][j][q] = 0.f;

    for (int kc = 0; kc < KCH; kc++) {
        bl_cp_wait<1>();
        __syncthreads();
        const int kn = kc + 2;
        if (kn < KCH)
            bl_load_stage(sb + (kn % 3) * STG, A + (size_t)kn * BKE,
                          B + (size_t)kn * BKE, tid);
        bl_cp_commit();

        const uint32_t abuf = sb + (kc % 3) * STG;
        const uint32_t bbuf = abuf + A_B;
#pragma unroll
        for (int ks = 0; ks < 4; ks++) {     // 4 x k16 steps (32 B each)
            uint32_t af[4][4];
#pragma unroll
            for (int mt = 0; mt < 4; mt++) {
                uint32_t ad = abuf + ((a_base + (uint32_t)(mt * 16 * 128)
                                        + (uint32_t)(ks * 32)) ^ a_xor);
                BL_LDSM4(af[mt][0], af[mt][1], af[mt][2], af[mt][3], ad);
            }
            uint32_t bf[4][2];
#pragma unroll
            for (int nt2 = 0; nt2 < 2; nt2++) {
                uint32_t bd = bbuf + ((b_base + (uint32_t)(nt2 * 16 * 128)
                                        + (uint32_t)(ks * 32)) ^ b_xor);
                uint32_t r0, r1, r2, r3;
                BL_LDSM4(r0, r1, r2, r3, bd);
                bf[nt2 * 2 + 0][0] = r0; bf[nt2 * 2 + 0][1] = r1;
                bf[nt2 * 2 + 1][0] = r2; bf[nt2 * 2 + 1][1] = r3;
            }
#pragma unroll
            for (int mt = 0; mt < 4; mt++)
#pragma unroll
                for (int nt = 0; nt < 4; nt++)
                    BL_MMA_BF16(acc[mt][nt], af[mt][0], af[mt][1], af[mt][2],
                                af[mt][3], bf[nt][0], bf[nt][1]);
        }
    }

    // epilogue: scale fp32 (exact integers) by rs[row] * mean|w|
    const float wp0 = bl_wp[0];
    const int gr = lane >> 2;
    const int gc = (lane & 3) * 2;
#pragma unroll
    for (int mt = 0; mt < 4; mt++) {
        const int row0 = m0 + warp_m * 64 + mt * 16 + gr;
        const int row1 = row0 + 8;
        const float s0 = bl_rs[row0] * wp0;
        const float s1 = bl_rs[row1] * wp0;
        float* p0 = out + (size_t)row0 * ND + n0 + warp_n * 32 + gc;
        float* p1 = out + (size_t)row1 * ND + n0 + warp_n * 32 + gc;
#pragma unroll
        for (int nt = 0; nt < 4; nt++) {
            *(float2*)(p0 + nt * 8) = make_float2(acc[mt][nt][0] * s0,
                                                  acc[mt][nt][1] * s0);
            *(float2*)(p1 + nt * 8) = make_float2(acc[mt][nt][2] * s1,
                                                  acc[mt][nt][3] * s1);
        }
    }
}

// ---------------- launcher ----------------
extern "C" void kernel_launch(void* const* d_in, const int* in_sizes, int n_in,
                              void* d_out, int out_size) {
    const float* x = (const float*)d_in[0];
    const float* w = (const float*)d_in[1];
    float* out = (float*)d_out;
    cudaFuncSetAttribute(bl_k_gemm, cudaFuncAttributeMaxDynamicSharedMemorySize, SMEM_SZ);
    bl_k_prep<<<10240, 256>>>(x, w);
    bl_k_wquant<<<2048, 256>>>(w);
    bl_k_gemm<<<(M_ROWS / BM) * (ND / BN), 256, SMEM_SZ>>>(out);
}

// round 12
// speedup vs baseline: 1.6846x; 1.0217x over previous
#include <cuda_runtime.h>
#include <cuda_bf16.h>
#include <cstdint>
#include <cstddef>

#define BL_EPS 1e-5f
static constexpr int    M_ROWS  = 8192;
static constexpr int    KD      = 4096;
static constexpr int    ND      = 16384;
static constexpr size_t W_ELEMS = (size_t)ND * KD;
static constexpr size_t X_ELEMS = (size_t)M_ROWS * KD;

// scratch (device globals: no allocations allowed)
__device__ __nv_bfloat16 bl_qx[X_ELEMS];   // quantized activations (integers in bf16)
__device__ __nv_bfloat16 bl_wq[W_ELEMS];   // ternary weights {-1,0,1} in bf16
__device__ float bl_rs[M_ROWS];            // per-row amax/127
__device__ float bl_part[2048];
__device__ float bl_wp[1];                 // clip(mean|w|, eps)

// ---------------- helpers ----------------
__device__ __forceinline__ uint32_t bl_cvta_s(const void* p) {
    uint32_t a;
    asm("{ .reg .u64 t; cvta.to.shared.u64 t, %1; cvt.u32.u64 %0, t; }" : "=r"(a) : "l"(p));
    return a;
}
__device__ __forceinline__ void bl_cp16(uint32_t s, const void* g) {
    asm volatile("cp.async.cg.shared.global [%0], [%1], 16;" :: "r"(s), "l"(g));
}
__device__ __forceinline__ void bl_cp_commit() { asm volatile("cp.async.commit_group;"); }
template <int N> __device__ __forceinline__ void bl_cp_wait() {
    asm volatile("cp.async.wait_group %0;" :: "n"(N));
}
#define BL_LDSM4(r0, r1, r2, r3, a)                                              \
    asm volatile("ldmatrix.sync.aligned.m8n8.x4.shared.b16 {%0,%1,%2,%3}, [%4];" \
                 : "=r"(r0), "=r"(r1), "=r"(r2), "=r"(r3) : "r"(a))
#define BL_MMA_BF16(d, a0, a1, a2, a3, b0, b1)                                   \
    asm volatile("mma.sync.aligned.m16n8k16.row.col.f32.bf16.bf16.f32 "          \
                 "{%0,%1,%2,%3}, {%4,%5,%6,%7}, {%8,%9}, {%0,%1,%2,%3};"         \
                 : "+f"((d)[0]), "+f"((d)[1]), "+f"((d)[2]), "+f"((d)[3])        \
                 : "r"(a0), "r"(a1), "r"(a2), "r"(a3), "r"(b0), "r"(b1))

__device__ __forceinline__ uint32_t bl_packbf2(float a, float b) {
    return (uint32_t)__bfloat16_as_ushort(__float2bfloat16_rn(a))
         | ((uint32_t)__bfloat16_as_ushort(__float2bfloat16_rn(b)) << 16);
}

// ---------------- prep kernels ----------------
// fused launch 1: blocks [0,8192) = per-row activation quant; [8192,10240) = |w| partials
__global__ void bl_k_prep(const float* __restrict__ x, const float* __restrict__ w) {
    __shared__ float red[256];
    if (blockIdx.x >= 8192) {               // |w| partial sums
        const int pb = blockIdx.x - 8192;   // 0..2047
        const float4* w4 = (const float4*)w;
        const size_t n4 = W_ELEMS / 4;
        float s = 0.f;
        for (size_t i = (size_t)pb * 256 + threadIdx.x; i < n4; i += (size_t)2048 * 256) {
            float4 v = w4[i];
            s += fabsf(v.x) + fabsf(v.y) + fabsf(v.z) + fabsf(v.w);
        }
        red[threadIdx.x] = s; __syncthreads();
        for (int o = 128; o > 0; o >>= 1) {
            if ((int)threadIdx.x < o) red[threadIdx.x] += red[threadIdx.x + o];
            __syncthreads();
        }
        if (threadIdx.x == 0) bl_part[pb] = red[0];
        return;
    }
    // activation quant for one row
    const int row = blockIdx.x;
    const float4* xr = (const float4*)(x + (size_t)row * KD);
    float4 v[4];
    float mx = 0.f;
#pragma unroll
    for (int i = 0; i < 4; i++) {
        v[i] = xr[threadIdx.x + i * 256];
        mx = fmaxf(mx, fmaxf(fmaxf(fabsf(v[i].x), fabsf(v[i].y)),
                             fmaxf(fabsf(v[i].z), fabsf(v[i].w))));
    }
    red[threadIdx.x] = mx; __syncthreads();
    for (int o = 128; o > 0; o >>= 1) {
        if ((int)threadIdx.x < o) red[threadIdx.x] = fmaxf(red[threadIdx.x], red[threadIdx.x + o]);
        __syncthreads();
    }
    const float amax  = fmaxf(red[0], BL_EPS);
    const float scale = 127.f / amax;
    if (threadIdx.x == 0) bl_rs[row] = amax * (1.f / 127.f);
    uint2* qr = (uint2*)(bl_qx + (size_t)row * KD);
#pragma unroll
    for (int i = 0; i < 4; i++) {
        float q0 = fminf(fmaxf(rintf(v[i].x * scale), -128.f), 127.f);
        float q1 = fminf(fmaxf(rintf(v[i].y * scale), -128.f), 127.f);
        float q2 = fminf(fmaxf(rintf(v[i].z * scale), -128.f), 127.f);
        float q3 = fminf(fmaxf(rintf(v[i].w * scale), -128.f), 127.f);
        uint2 o;
        o.x = bl_packbf2(q0, q1);
        o.y = bl_packbf2(q2, q3);
        qr[threadIdx.x + i * 256] = o;
    }
}

// fused: every block reduces bl_part identically (deterministic), then quantizes.
__global__ void bl_k_wquant(const float* __restrict__ w) {
    __shared__ float red[256];
    float s = 0.f;
#pragma unroll
    for (int i = 0; i < 8; i++) s += bl_part[threadIdx.x * 8 + i];
    red[threadIdx.x] = s; __syncthreads();
    for (int o = 128; o > 0; o >>= 1) {
        if ((int)threadIdx.x < o) red[threadIdx.x] += red[threadIdx.x + o];
        __syncthreads();
    }
    const float m = fmaxf(red[0] / (float)W_ELEMS, BL_EPS);
    const float sc = 1.f / m;
    if (blockIdx.x == 0 && threadIdx.x == 0) bl_wp[0] = m;

    const float4* w4 = (const float4*)w;
    uint2* out = (uint2*)bl_wq;
    const size_t n4 = W_ELEMS / 4;
    for (size_t i = (size_t)blockIdx.x * 256 + threadIdx.x; i < n4; i += (size_t)2048 * 256) {
        float4 v = w4[i];
        float q0 = fminf(fmaxf(rintf(v.x * sc), -1.f), 1.f);
        float q1 = fminf(fmaxf(rintf(v.y * sc), -1.f), 1.f);
        float q2 = fminf(fmaxf(rintf(v.z * sc), -1.f), 1.f);
        float q3 = fminf(fmaxf(rintf(v.w * sc), -1.f), 1.f);
        uint2 o;
        o.x = bl_packbf2(q0, q1);
        o.y = bl_packbf2(q2, q3);
        out[i] = o;
    }
}

// ---------------- bf16 HMMA GEMM ----------------
// CTA tile 128(M) x 128(N), BK = 64 bf16 (128 B rows), 3-stage cp.async.
// 8 warps (256 thr), warp grid 2(M) x 4(N), warp tile 64 x 32.
// 2 CTAs per SM, phase-staggered; next-chunk loads issued after the first
// k16 step so post-barrier LDSM/MMA restart immediately.
static constexpr int BM = 128, BN = 128, BKE = 64;
static constexpr int KCH   = KD / BKE;               // 64 chunks
static constexpr int A_B   = BM * 128;               // 16 KB
static constexpr int B_B   = BN * 128;               // 16 KB
static constexpr int STG   = A_B + B_B;              // 32 KB
static constexpr int SMEM_SZ = 3 * STG;              // 98304 (x2 CTAs = 192 KB/SM)

#define BL_SWZ_MASK(row) ((uint32_t)(((row) & 7) << 4))

__device__ __forceinline__ void bl_load_stage(uint32_t base, const __nv_bfloat16* a,
                                              const __nv_bfloat16* b, int tid) {
#pragma unroll
    for (int i = 0; i < 4; i++) {            // A: 128 rows x 128 B = 1024 x 16 B
        int s = tid + i * 256;
        int rr = s >> 3, j = s & 7;
        uint32_t off = (uint32_t)(rr * 128 + j * 16);
        bl_cp16(base + (off ^ BL_SWZ_MASK(rr)), a + (size_t)rr * KD + j * 8);
    }
    uint32_t bb = base + A_B;
#pragma unroll
    for (int i = 0; i < 4; i++) {            // B: 128 rows x 128 B
        int s = tid + i * 256;
        int rr = s >> 3, j = s & 7;
        uint32_t off = (uint32_t)(rr * 128 + j * 16);
        bl_cp16(bb + (off ^ BL_SWZ_MASK(rr)), b + (size_t)rr * KD + j * 8);
    }
}

__global__ void __launch_bounds__(256, 2) bl_k_gemm(float* __restrict__ out) {
    extern __shared__ char smem[];
    const uint32_t sb = bl_cvta_s(smem);
    const int tid  = threadIdx.x;
    const int wid  = tid >> 5, lane = tid & 31;
    const int warp_m = wid & 1;              // 0..1 -> 64 rows
    const int warp_n = wid >> 1;             // 0..3 -> 32 cols

    // supertile swizzle: bands of 16 M-tiles, sweep all 128 N-tiles per band
    const int bid  = blockIdx.x;
    const int band = bid >> 11;              // / (16*128)
    const int r    = bid & 2047;
    const int mt_  = band * 16 + (r & 15);
    const int nt_  = r >> 4;
    const int m0 = mt_ * BM, n0 = nt_ * BN;

    const __nv_bfloat16* A = bl_qx + (size_t)m0 * KD;
    const __nv_bfloat16* B = bl_wq + (size_t)n0 * KD;

    bl_load_stage(sb + 0 * STG, A, B, tid);              bl_cp_commit();
    bl_load_stage(sb + 1 * STG, A + BKE, B + BKE, tid);  bl_cp_commit();

    // Hoist epilogue scales: hide the LDG latency behind the mainloop.
    const float wp0 = bl_wp[0];
    const int gr = lane >> 2;
    const int gc = (lane & 3) * 2;
    const int erow0 = m0 + warp_m * 64 + gr;   // + mt*16 in epilogue
    float esc[8];
#pragma unroll
    for (int mt = 0; mt < 4; mt++) {
        esc[mt * 2 + 0] = bl_rs[erow0 + mt * 16] * wp0;
        esc[mt * 2 + 1] = bl_rs[erow0 + mt * 16 + 8] * wp0;
    }

    // Phase-stagger one CTA of each co-resident pair (classic placement pairs
    // bid with bid+148); offset ~half the per-CTA chunk period (2048 cyc).
    if (((bid / 148) & 1) != 0) {
        unsigned long long t0 = clock64();
        while (clock64() - t0 < 1024ull) {}
    }

    // ldmatrix lane addressing (16-B granule swizzle; 16 B = 8 bf16 = k8)
    const int lm = lane >> 3;                // matrix 0..3 within .x4
    const int l8 = lane & 7;
    // A matrices: {r+0 k0-7}, {r+8 k0-7}, {r+0 k8-15}, {r+8 k8-15} -> a0..a3
    const int a_row  = warp_m * 64 + (lm & 1) * 8 + l8;
    const uint32_t a_xor  = BL_SWZ_MASK(a_row);
    const uint32_t a_base = (uint32_t)(a_row * 128) + (uint32_t)((lm >> 1) * 16);
    // B matrices: {n+0 k0-7}, {n+0 k8-15}, {n+8 k0-7}, {n+8 k8-15}
    const int b_row  = warp_n * 32 + (lm >> 1) * 8 + l8;
    const uint32_t b_xor  = BL_SWZ_MASK(b_row);
    const uint32_t b_base = (uint32_t)(b_row * 128) + (uint32_t)((lm & 1) * 16);

    float acc[4][4][4];
#pragma unroll
    for (int i = 0; i < 4; i++)
#pragma unroll
        for (int j = 0; j < 4; j++)
#pragma unroll
            for (int q = 0; q < 4; q++) acc[i][j][q] = 0.f;

    for (int kc = 0; kc < KCH; kc++) {
        bl_cp_wait<1>();
        __syncthreads();

        const uint32_t abuf = sb + (kc % 3) * STG;
        const uint32_t bbuf = abuf + A_B;
        const int kn = kc + 2;
#pragma unroll
        for (int ks = 0; ks < 4; ks++) {     // 4 x k16 steps (32 B each)
            uint32_t af[4][4];
#pragma unroll
            for (int mt = 0; mt < 4; mt++) {
                uint32_t ad = abuf + ((a_base + (uint32_t)(mt * 16 * 128)
                                        + (uint32_t)(ks * 32)) ^ a_xor);
                BL_LDSM4(af[mt][0], af[mt][1], af[mt][2], af[mt][3], ad);
            }
            uint32_t bf[4][2];
#pragma unroll
            for (int nt2 = 0; nt2 < 2; nt2++) {
                uint32_t bd = bbuf + ((b_base + (uint32_t)(nt2 * 16 * 128)
                                        + (uint32_t)(ks * 32)) ^ b_xor);
                uint32_t r0, r1, r2, r3;
                BL_LDSM4(r0, r1, r2, r3, bd);
                bf[nt2 * 2 + 0][0] = r0; bf[nt2 * 2 + 0][1] = r1;
                bf[nt2 * 2 + 1][0] = r2; bf[nt2 * 2 + 1][1] = r3;
            }
#pragma unroll
            for (int mt = 0; mt < 4; mt++)
#pragma unroll
                for (int nt = 0; nt < 4; nt++)
                    BL_MMA_BF16(acc[mt][nt], af[mt][0], af[mt][1], af[mt][2],
                                af[mt][3], bf[nt][0], bf[nt][1]);

            // issue next-chunk loads AFTER the first k16 step: LDSM/MMA restart
            // immediately post-barrier; the cp.async burst overlaps full tensor queue
            if (ks == 0) {
                if (kn < KCH)
                    bl_load_stage(sb + (kn % 3) * STG, A + (size_t)kn * BKE,
                                  B + (size_t)kn * BKE, tid);
                bl_cp_commit();
            }
        }
    }

    // epilogue: scale fp32 (exact integers) by rs[row] * mean|w|
#pragma unroll
    for (int mt = 0; mt < 4; mt++) {
        const int row0 = m0 + warp_m * 64 + mt * 16 + gr;
        const int row1 = row0 + 8;
        const float s0 = esc[mt * 2 + 0];
        const float s1 = esc[mt * 2 + 1];
        float* p0 = out + (size_t)row0 * ND + n0 + warp_n * 32 + gc;
        float* p1 = out + (size_t)row1 * ND + n0 + warp_n * 32 + gc;
#pragma unroll
        for (int nt = 0; nt < 4; nt++) {
            *(float2*)(p0 + nt * 8) = make_float2(acc[mt][nt][0] * s0,
                                                  acc[mt][nt][1] * s0);
            *(float2*)(p1 + nt * 8) = make_float2(acc[mt][nt][2] * s1,
                                                  acc[mt][nt][3] * s1);
        }
    }
}

// ---------------- launcher ----------------
extern "C" void kernel_launch(void* const* d_in, const int* in_sizes, int n_in,
                              void* d_out, int out_size) {
    const float* x = (const float*)d_in[0];
    const float* w = (const float*)d_in[1];
    float* out = (float*)d_out;
    cudaFuncSetAttribute(bl_k_gemm, cudaFuncAttributeMaxDynamicSharedMemorySize, SMEM_SZ);
    bl_k_prep<<<10240, 256>>>(x, w);
    bl_k_wquant<<<2048, 256>>>(w);
    bl_k_gemm<<<(M_ROWS / BM) * (ND / BN), 256, SMEM_SZ>>>(out);
}

// round 13
// speedup vs baseline: 1.6853x; 1.0004x over previous
#include <cuda_runtime.h>
#include <cuda_bf16.h>
#include <cstdint>
#include <cstddef>

#define BL_EPS 1e-5f
static constexpr int    M_ROWS  = 8192;
static constexpr int    KD      = 4096;
static constexpr int    ND      = 16384;
static constexpr size_t W_ELEMS = (size_t)ND * KD;
static constexpr size_t X_ELEMS = (size_t)M_ROWS * KD;

// scratch (device globals: no allocations allowed)
__device__ __nv_bfloat16 bl_qx[X_ELEMS];   // quantized activations (integers in bf16)
__device__ __nv_bfloat16 bl_wq[W_ELEMS];   // ternary weights {-1,0,1} in bf16
__device__ float bl_rs[M_ROWS];            // per-row amax/127
__device__ float bl_part[2048];
__device__ float bl_wp[1];                 // clip(mean|w|, eps)

// ---------------- helpers ----------------
__device__ __forceinline__ uint32_t bl_cvta_s(const void* p) {
    uint32_t a;
    asm("{ .reg .u64 t; cvta.to.shared.u64 t, %1; cvt.u32.u64 %0, t; }" : "=r"(a) : "l"(p));
    return a;
}
__device__ __forceinline__ void bl_cp16(uint32_t s, const void* g) {
    asm volatile("cp.async.cg.shared.global [%0], [%1], 16;" :: "r"(s), "l"(g));
}
__device__ __forceinline__ void bl_cp_commit() { asm volatile("cp.async.commit_group;"); }
template <int N> __device__ __forceinline__ void bl_cp_wait() {
    asm volatile("cp.async.wait_group %0;" :: "n"(N));
}
#define BL_LDSM4(r0, r1, r2, r3, a)                                              \
    asm volatile("ldmatrix.sync.aligned.m8n8.x4.shared.b16 {%0,%1,%2,%3}, [%4];" \
                 : "=r"(r0), "=r"(r1), "=r"(r2), "=r"(r3) : "r"(a))
#define BL_MMA_BF16(d, a0, a1, a2, a3, b0, b1)                                   \
    asm volatile("mma.sync.aligned.m16n8k16.row.col.f32.bf16.bf16.f32 "          \
                 "{%0,%1,%2,%3}, {%4,%5,%6,%7}, {%8,%9}, {%0,%1,%2,%3};"         \
                 : "+f"((d)[0]), "+f"((d)[1]), "+f"((d)[2]), "+f"((d)[3])        \
                 : "r"(a0), "r"(a1), "r"(a2), "r"(a3), "r"(b0), "r"(b1))

__device__ __forceinline__ uint32_t bl_packbf2(float a, float b) {
    return (uint32_t)__bfloat16_as_ushort(__float2bfloat16_rn(a))
         | ((uint32_t)__bfloat16_as_ushort(__float2bfloat16_rn(b)) << 16);
}

// ---------------- prep kernels ----------------
// fused launch 1: blocks [0,8192) = per-row activation quant; [8192,10240) = |w| partials
__global__ void bl_k_prep(const float* __restrict__ x, const float* __restrict__ w) {
    __shared__ float red[256];
    if (blockIdx.x >= 8192) {               // |w| partial sums
        const int pb = blockIdx.x - 8192;   // 0..2047
        const float4* w4 = (const float4*)w;
        const size_t n4 = W_ELEMS / 4;
        float s = 0.f;
        for (size_t i = (size_t)pb * 256 + threadIdx.x; i < n4; i += (size_t)2048 * 256) {
            float4 v = w4[i];
            s += fabsf(v.x) + fabsf(v.y) + fabsf(v.z) + fabsf(v.w);
        }
        red[threadIdx.x] = s; __syncthreads();
        for (int o = 128; o > 0; o >>= 1) {
            if ((int)threadIdx.x < o) red[threadIdx.x] += red[threadIdx.x + o];
            __syncthreads();
        }
        if (threadIdx.x == 0) bl_part[pb] = red[0];
        return;
    }
    // activation quant for one row
    const int row = blockIdx.x;
    const float4* xr = (const float4*)(x + (size_t)row * KD);
    float4 v[4];
    float mx = 0.f;
#pragma unroll
    for (int i = 0; i < 4; i++) {
        v[i] = xr[threadIdx.x + i * 256];
        mx = fmaxf(mx, fmaxf(fmaxf(fabsf(v[i].x), fabsf(v[i].y)),
                             fmaxf(fabsf(v[i].z), fabsf(v[i].w))));
    }
    red[threadIdx.x] = mx; __syncthreads();
    for (int o = 128; o > 0; o >>= 1) {
        if ((int)threadIdx.x < o) red[threadIdx.x] = fmaxf(red[threadIdx.x], red[threadIdx.x + o]);
        __syncthreads();
    }
    const float amax  = fmaxf(red[0], BL_EPS);
    const float scale = 127.f / amax;
    if (threadIdx.x == 0) bl_rs[row] = amax * (1.f / 127.f);
    uint2* qr = (uint2*)(bl_qx + (size_t)row * KD);
#pragma unroll
    for (int i = 0; i < 4; i++) {
        float q0 = fminf(fmaxf(rintf(v[i].x * scale), -128.f), 127.f);
        float q1 = fminf(fmaxf(rintf(v[i].y * scale), -128.f), 127.f);
        float q2 = fminf(fmaxf(rintf(v[i].z * scale), -128.f), 127.f);
        float q3 = fminf(fmaxf(rintf(v[i].w * scale), -128.f), 127.f);
        uint2 o;
        o.x = bl_packbf2(q0, q1);
        o.y = bl_packbf2(q2, q3);
        qr[threadIdx.x + i * 256] = o;
    }
}

// fused: every block reduces bl_part identically (deterministic), then quantizes.
__global__ void bl_k_wquant(const float* __restrict__ w) {
    __shared__ float red[256];
    float s = 0.f;
#pragma unroll
    for (int i = 0; i < 8; i++) s += bl_part[threadIdx.x * 8 + i];
    red[threadIdx.x] = s; __syncthreads();
    for (int o = 128; o > 0; o >>= 1) {
        if ((int)threadIdx.x < o) red[threadIdx.x] += red[threadIdx.x + o];
        __syncthreads();
    }
    const float m = fmaxf(red[0] / (float)W_ELEMS, BL_EPS);
    const float sc = 1.f / m;
    if (blockIdx.x == 0 && threadIdx.x == 0) bl_wp[0] = m;

    const float4* w4 = (const float4*)w;
    uint2* out = (uint2*)bl_wq;
    const size_t n4 = W_ELEMS / 4;
    for (size_t i = (size_t)blockIdx.x * 256 + threadIdx.x; i < n4; i += (size_t)2048 * 256) {
        float4 v = w4[i];
        float q0 = fminf(fmaxf(rintf(v.x * sc), -1.f), 1.f);
        float q1 = fminf(fmaxf(rintf(v.y * sc), -1.f), 1.f);
        float q2 = fminf(fmaxf(rintf(v.z * sc), -1.f), 1.f);
        float q3 = fminf(fmaxf(rintf(v.w * sc), -1.f), 1.f);
        uint2 o;
        o.x = bl_packbf2(q0, q1);
        o.y = bl_packbf2(q2, q3);
        out[i] = o;
    }
}

// ---------------- bf16 HMMA GEMM ----------------
// CTA tile 128(M) x 128(N), BK = 64 bf16 (128 B rows), 3-stage cp.async.
// 8 warps (256 thr), warp grid 2(M) x 4(N), warp tile 64 x 32, 2 CTAs/SM.
// The variable-latency cp.async wait is issued mid-MMA-stream (after the
// ks=0 prefetch) so the top-of-loop barrier is a pure rendezvous.
static constexpr int BM = 128, BN = 128, BKE = 64;
static constexpr int KCH   = KD / BKE;               // 64 chunks
static constexpr int A_B   = BM * 128;               // 16 KB
static constexpr int B_B   = BN * 128;               // 16 KB
static constexpr int STG   = A_B + B_B;              // 32 KB
static constexpr int SMEM_SZ = 3 * STG;              // 98304 (x2 CTAs = 192 KB/SM)

#define BL_SWZ_MASK(row) ((uint32_t)(((row) & 7) << 4))

__device__ __forceinline__ void bl_load_stage(uint32_t base, const __nv_bfloat16* a,
                                              const __nv_bfloat16* b, int tid) {
#pragma unroll
    for (int i = 0; i < 4; i++) {            // A: 128 rows x 128 B = 1024 x 16 B
        int s = tid + i * 256;
        int rr = s >> 3, j = s & 7;
        uint32_t off = (uint32_t)(rr * 128 + j * 16);
        bl_cp16(base + (off ^ BL_SWZ_MASK(rr)), a + (size_t)rr * KD + j * 8);
    }
    uint32_t bb = base + A_B;
#pragma unroll
    for (int i = 0; i < 4; i++) {            // B: 128 rows x 128 B
        int s = tid + i * 256;
        int rr = s >> 3, j = s & 7;
        uint32_t off = (uint32_t)(rr * 128 + j * 16);
        bl_cp16(bb + (off ^ BL_SWZ_MASK(rr)), b + (size_t)rr * KD + j * 8);
    }
}

__global__ void __launch_bounds__(256, 2) bl_k_gemm(float* __restrict__ out) {
    extern __shared__ char smem[];
    const uint32_t sb = bl_cvta_s(smem);
    const int tid  = threadIdx.x;
    const int wid  = tid >> 5, lane = tid & 31;
    const int warp_m = wid & 1;              // 0..1 -> 64 rows
    const int warp_n = wid >> 1;             // 0..3 -> 32 cols

    // supertile swizzle: bands of 16 M-tiles, sweep all 128 N-tiles per band
    const int bid  = blockIdx.x;
    const int band = bid >> 11;              // / (16*128)
    const int r    = bid & 2047;
    const int mt_  = band * 16 + (r & 15);
    const int nt_  = r >> 4;
    const int m0 = mt_ * BM, n0 = nt_ * BN;

    const __nv_bfloat16* A = bl_qx + (size_t)m0 * KD;
    const __nv_bfloat16* B = bl_wq + (size_t)n0 * KD;

    bl_load_stage(sb + 0 * STG, A, B, tid);              bl_cp_commit();
    bl_load_stage(sb + 1 * STG, A + BKE, B + BKE, tid);  bl_cp_commit();

    // Hoist epilogue scales: hide the LDG latency behind the mainloop.
    const float wp0 = bl_wp[0];
    const int gr = lane >> 2;
    const int gc = (lane & 3) * 2;
    const int erow0 = m0 + warp_m * 64 + gr;   // + mt*16 in epilogue
    float esc[8];
#pragma unroll
    for (int mt = 0; mt < 4; mt++) {
        esc[mt * 2 + 0] = bl_rs[erow0 + mt * 16] * wp0;
        esc[mt * 2 + 1] = bl_rs[erow0 + mt * 16 + 8] * wp0;
    }

    // Phase-stagger one CTA of each co-resident pair (classic placement pairs
    // bid with bid+148); offset ~half the per-CTA chunk period.
    if (((bid / 148) & 1) != 0) {
        unsigned long long t0 = clock64();
        while (clock64() - t0 < 1024ull) {}
    }

    // prologue wait: chunk 0 resident per-thread before the first rendezvous
    bl_cp_wait<1>();

    // ldmatrix lane addressing (16-B granule swizzle; 16 B = 8 bf16 = k8)
    const int lm = lane >> 3;                // matrix 0..3 within .x4
    const int l8 = lane & 7;
    // A matrices: {r+0 k0-7}, {r+8 k0-7}, {r+0 k8-15}, {r+8 k8-15} -> a0..a3
    const int a_row  = warp_m * 64 + (lm & 1) * 8 + l8;
    const uint32_t a_xor  = BL_SWZ_MASK(a_row);
    const uint32_t a_base = (uint32_t)(a_row * 128) + (uint32_t)((lm >> 1) * 16);
    // B matrices: {n+0 k0-7}, {n+0 k8-15}, {n+8 k0-7}, {n+8 k8-15}
    const int b_row  = warp_n * 32 + (lm >> 1) * 8 + l8;
    const uint32_t b_xor  = BL_SWZ_MASK(b_row);
    const uint32_t b_base = (uint32_t)(b_row * 128) + (uint32_t)((lm & 1) * 16);

    float acc[4][4][4];
#pragma unroll
    for (int i = 0; i < 4; i++)
#pragma unroll
        for (int j = 0; j < 4; j++)
#pragma unroll
            for (int q = 0; q < 4; q++) acc[i][j][q] = 0.f;

    for (int kc = 0; kc < KCH; kc++) {
        // pure rendezvous: every thread already verified its chunk-kc copies
        __syncthreads();

        const uint32_t abuf = sb + (kc % 3) * STG;
        const uint32_t bbuf = abuf + A_B;
        const int kn = kc + 2;
#pragma unroll
        for (int ks = 0; ks < 4; ks++) {     // 4 x k16 steps (32 B each)
            uint32_t af[4][4];
#pragma unroll
            for (int mt = 0; mt < 4; mt++) {
                uint32_t ad = abuf + ((a_base + (uint32_t)(mt * 16 * 128)
                                        + (uint32_t)(ks * 32)) ^ a_xor);
                BL_LDSM4(af[mt][0], af[mt][1], af[mt][2], af[mt][3], ad);
            }
            uint32_t bf[4][2];
#pragma unroll
            for (int nt2 = 0; nt2 < 2; nt2++) {
                uint32_t bd = bbuf + ((b_base + (uint32_t)(nt2 * 16 * 128)
                                        + (uint32_t)(ks * 32)) ^ b_xor);
                uint32_t r0, r1, r2, r3;
                BL_LDSM4(r0, r1, r2, r3, bd);
                bf[nt2 * 2 + 0][0] = r0; bf[nt2 * 2 + 0][1] = r1;
                bf[nt2 * 2 + 1][0] = r2; bf[nt2 * 2 + 1][1] = r3;
            }
#pragma unroll
            for (int mt = 0; mt < 4; mt++)
#pragma unroll
                for (int nt = 0; nt < 4; nt++)
                    BL_MMA_BF16(acc[mt][nt], af[mt][0], af[mt][1], af[mt][2],
                                af[mt][3], bf[nt][0], bf[nt][1]);

            // after the first k16 step: issue next-chunk loads, then retire the
            // wait for chunk kc+1 while 3 more k16 steps of MMA cover it
            if (ks == 0) {
                if (kn < KCH)
                    bl_load_stage(sb + (kn % 3) * STG, A + (size_t)kn * BKE,
                                  B + (size_t)kn * BKE, tid);
                bl_cp_commit();
                bl_cp_wait<1>();
            }
        }
    }

    // epilogue: scale fp32 (exact integers) by rs[row] * mean|w|
#pragma unroll
    for (int mt = 0; mt < 4; mt++) {
        const int row0 = m0 + warp_m * 64 + mt * 16 + gr;
        const int row1 = row0 + 8;
        const float s0 = esc[mt * 2 + 0];
        const float s1 = esc[mt * 2 + 1];
        float* p0 = out + (size_t)row0 * ND + n0 + warp_n * 32 + gc;
        float* p1 = out + (size_t)row1 * ND + n0 + warp_n * 32 + gc;
#pragma unroll
        for (int nt = 0; nt < 4; nt++) {
            *(float2*)(p0 + nt * 8) = make_float2(acc[mt][nt][0] * s0,
                                                  acc[mt][nt][1] * s0);
            *(float2*)(p1 + nt * 8) = make_float2(acc[mt][nt][2] * s1,
                                                  acc[mt][nt][3] * s1);
        }
    }
}

// ---------------- launcher ----------------
extern "C" void kernel_launch(void* const* d_in, const int* in_sizes, int n_in,
                              void* d_out, int out_size) {
    const float* x = (const float*)d_in[0];
    const float* w = (const float*)d_in[1];
    float* out = (float*)d_out;
    cudaFuncSetAttribute(bl_k_gemm, cudaFuncAttributeMaxDynamicSharedMemorySize, SMEM_SZ);
    bl_k_prep<<<10240, 256>>>(x, w);
    bl_k_wquant<<<2048, 256>>>(w);
    bl_k_gemm<<<(M_ROWS / BM) * (ND / BN), 256, SMEM_SZ>>>(out);
}